// round 1
// baseline (speedup 1.0000x reference)
#include <cuda_runtime.h>
#include <math.h>

#define GRIDN 17
#define NV    289          // 17*17 vertices
#define NF    512          // faces
#define IMG   128
#define KF    8

// Per-face main data (21 floats):
// 0:ax 1:ay 2:bx 3:by 4:cx 5:cy 6:z0 7:z1 8:z2 9:inv_area
// 10:z1*z2 11:z0*z2 12:z0*z1 13:u0 14:v0 15:u1 16:v1 17:u2 18:v2 19:bbx0 20:bbx1
__device__ float g_main[NF * 21];
__device__ float g_bby[NF * 2];   // y bbox (dilated by blur distance)

__device__ __forceinline__ int vid(int y, int x) { return y * GRIDN + x; }

__device__ __forceinline__ void face_idx(int f, int& i0, int& i1, int& i2) {
    int g = f >> 6, t = f & 63;
    int r = t >> 3, c = t & 7;
    int ny, nx;
    switch (g) {
        case 0:  ny = 2*r;   nx = 1+2*c; i0 = vid(ny,nx+1);   i1 = vid(ny,nx);   i2 = vid(ny+1,nx);   break;
        case 1:  ny = 2*r;   nx = 1+2*c; i0 = vid(ny,nx+1);   i1 = vid(ny+1,nx); i2 = vid(ny+1,nx+1); break;
        case 2:  ny = 2*r;   nx = 2*c;   i0 = vid(ny,nx+1);   i1 = vid(ny,nx);   i2 = vid(ny+1,nx+1); break;
        case 3:  ny = 2*r;   nx = 2*c;   i0 = vid(ny+1,nx+1); i1 = vid(ny,nx);   i2 = vid(ny+1,nx);   break;
        case 4:  ny = 1+2*r; nx = 2*c;   i0 = vid(ny,nx+1);   i1 = vid(ny,nx);   i2 = vid(ny+1,nx);   break;
        case 5:  ny = 1+2*r; nx = 2*c;   i0 = vid(ny,nx+1);   i1 = vid(ny+1,nx); i2 = vid(ny+1,nx+1); break;
        case 6:  ny = 1+2*r; nx = 1+2*c; i0 = vid(ny,nx+1);   i1 = vid(ny,nx);   i2 = vid(ny+1,nx+1); break;
        default: ny = 1+2*r; nx = 1+2*c; i0 = vid(ny+1,nx+1); i1 = vid(ny,nx);   i2 = vid(ny+1,nx);   break;
    }
}

// ---------------------------------------------------------------------------
// Kernel 1: vertex transform + per-face precompute.  <<<1, 512>>>
// ---------------------------------------------------------------------------
__global__ void setup_kernel(const float* __restrict__ xy_off,   // (1,289,2)
                             const float* __restrict__ z_grid,   // (1,289,1)
                             const float* __restrict__ R_in,     // (1,3,3)
                             const float* __restrict__ T_in,     // (1,3)
                             const float* __restrict__ R_out,    // (1,3,3)
                             const float* __restrict__ T_out)    // (1,3)
{
    const float SCALE = 0.57735026918962573f;     // tan(30 deg), f32-rounded
    const float SINV  = 1.0f / 0.57735026918962573f;

    __shared__ float ssx[NV], ssy[NV], ssz[NV];
    int t = threadIdx.x;

    if (t < NV) {
        int vy = t / GRIDN, vx = t % GRIDN;
        float ux = -1.0f + 0.125f * (float)vx;    // linspace(-1,1,17) exact
        float uy = -1.0f + 0.125f * (float)vy;
        float gx = (ux + xy_off[2*t + 0]) * SCALE;
        float gy = (uy + xy_off[2*t + 1]) * SCALE;
        float zg = z_grid[t];
        float s0 = gx * zg, s1 = gy * zg, s2 = zg;
        // subtract T_in, multiply R_in (world_k = sum_j (sv-T)_j * R_in[k][j])
        float q0 = s0 - T_in[0], q1 = s1 - T_in[1], q2 = s2 - T_in[2];
        float wx = R_in[0]*q0 + R_in[1]*q1 + R_in[2]*q2;
        float wy = R_in[3]*q0 + R_in[4]*q1 + R_in[5]*q2;
        float wz = R_in[6]*q0 + R_in[7]*q1 + R_in[8]*q2;
        // view_k = sum_j world_j * R_out[j][k] + T_out[k]
        float vxv = wx*R_out[0] + wy*R_out[3] + wz*R_out[6] + T_out[0];
        float vyv = wx*R_out[1] + wy*R_out[4] + wz*R_out[7] + T_out[1];
        float vzv = wx*R_out[2] + wy*R_out[5] + wz*R_out[8] + T_out[2];
        float zden = (vzv >= 0.0f) ? fmaxf(vzv, 0.01f) : fminf(vzv, -0.01f);
        ssx[t] = SINV * vxv / zden;
        ssy[t] = SINV * vyv / zden;
        ssz[t] = vzv;
    }
    __syncthreads();

    int f = t;  // 512 threads == 512 faces
    int i0, i1, i2;
    face_idx(f, i0, i1, i2);

    float ax = ssx[i0], ay = ssy[i0], z0 = ssz[i0];
    float bx = ssx[i1], by = ssy[i1], z1 = ssz[i1];
    float cx = ssx[i2], cy = ssy[i2], z2 = ssz[i2];

    float area = (bx - ax) * (cy - ay) - (by - ay) * (cx - ax);
    float area_s = (fabsf(area) < 1e-8f) ? 1e-8f : area;

    // UVs: x_uv = 1 - vx/16, y_uv = vy/16  (exact binary values)
    float u0 = 1.0f - 0.0625f * (float)(i0 % GRIDN), v0 = 0.0625f * (float)(i0 / GRIDN);
    float u1 = 1.0f - 0.0625f * (float)(i1 % GRIDN), v1 = 0.0625f * (float)(i1 / GRIDN);
    float u2 = 1.0f - 0.0625f * (float)(i2 % GRIDN), v2 = 0.0625f * (float)(i2 / GRIDN);

    // bbox dilated by sqrt(BLUR_RADIUS)=0.01 (+ epsilon for fp safety)
    const float M = 0.010001f;
    float bbx0 = fminf(fminf(ax, bx), cx) - M;
    float bbx1 = fmaxf(fmaxf(ax, bx), cx) + M;
    float bby0 = fminf(fminf(ay, by), cy) - M;
    float bby1 = fmaxf(fmaxf(ay, by), cy) + M;

    float* fd = &g_main[f * 21];
    fd[0]=ax; fd[1]=ay; fd[2]=bx; fd[3]=by; fd[4]=cx; fd[5]=cy;
    fd[6]=z0; fd[7]=z1; fd[8]=z2;
    fd[9]=1.0f/area_s;
    fd[10]=z1*z2; fd[11]=z0*z2; fd[12]=z0*z1;
    fd[13]=u0; fd[14]=v0; fd[15]=u1; fd[16]=v1; fd[17]=u2; fd[18]=v2;
    fd[19]=bbx0; fd[20]=bbx1;
    g_bby[2*f + 0] = bby0;
    g_bby[2*f + 1] = bby1;
}

__device__ __forceinline__ float seg_d2(float px, float py,
                                        float sx, float sy, float ex, float ey) {
    float dx = ex - sx, dy = ey - sy;
    float dd = fmaxf(dx*dx + dy*dy, 1e-12f);
    float tt = ((px - sx)*dx + (py - sy)*dy) / dd;
    tt = fminf(fmaxf(tt, 0.0f), 1.0f);
    float qx = px - (sx + tt*dx), qy = py - (sy + tt*dy);
    return qx*qx + qy*qy;
}

// ---------------------------------------------------------------------------
// Kernel 2: rasterize + shade.  <<<128, 128>>> — one row per block.
// ---------------------------------------------------------------------------
__global__ void __launch_bounds__(128) raster_kernel(const float* __restrict__ tex,
                                                     float* __restrict__ out)
{
    __shared__ float s_main[NF * 21];       // 43008 B
    __shared__ int   s_list[NF];
    __shared__ int   s_cnt;

    int x = threadIdx.x;
    int y = blockIdx.x;
    float py = 1.0f - 2.0f * ((float)y + 0.5f) / 128.0f;
    float px = 1.0f - 2.0f * ((float)x + 0.5f) / 128.0f;

    if (threadIdx.x == 0) s_cnt = 0;
    // stage all face data in shared (coalesced; broadcast LDS in the loop)
    for (int i = threadIdx.x; i < NF * 21; i += blockDim.x) s_main[i] = g_main[i];
    __syncthreads();

    // block-level y-bbox compaction (py uniform over block)
    for (int f = threadIdx.x; f < NF; f += blockDim.x) {
        float y0 = g_bby[2*f], y1 = g_bby[2*f + 1];
        if (py >= y0 && py <= y1) {
            int pos = atomicAdd(&s_cnt, 1);
            s_list[pos] = f;
        }
    }
    __syncthreads();
    int cnt = s_cnt;

    // top-8 by (z, face index) lexicographic — order-independent, matches
    // lax.top_k tie semantics (lowest index wins on equal z).
    float tz[KF], td[KF], tu[KF], tv[KF];
    int   ti[KF];
    #pragma unroll
    for (int k = 0; k < KF; k++) {
        tz[k] = __int_as_float(0x7f800000);  // +inf
        td[k] = 0.0f; tu[k] = 0.0f; tv[k] = 0.0f; ti[k] = 0x7fffffff;
    }

    for (int i = 0; i < cnt; i++) {
        int f = s_list[i];
        const float* fd = &s_main[f * 21];
        float bx0 = fd[19], bx1 = fd[20];
        if (px < bx0 || px > bx1) continue;

        float ax = fd[0], ay = fd[1], bx = fd[2], by = fd[3], cx = fd[4], cy = fd[5];
        float z0 = fd[6], z1 = fd[7], z2 = fd[8];
        float inv_area = fd[9];
        float z12 = fd[10], z02 = fd[11], z01 = fd[12];

        float w0 = (bx - px)*(cy - py) - (by - py)*(cx - px);
        float w1 = (cx - px)*(ay - py) - (cy - py)*(ax - px);
        float w2 = (ax - px)*(by - py) - (ay - py)*(bx - px);
        float b0 = w0 * inv_area, b1 = w1 * inv_area, b2 = w2 * inv_area;
        bool inside = (b0 >= 0.0f) && (b1 >= 0.0f) && (b2 >= 0.0f);

        float n0 = b0 * z12, n1 = b1 * z02, n2 = b2 * z01;
        float den = n0 + n1 + n2;
        den = (fabsf(den) < 1e-10f) ? 1e-10f : den;
        float p0 = n0 / den, p1 = n1 / den, p2 = n2 / den;
        float c0 = fmaxf(p0, 0.0f), c1 = fmaxf(p1, 0.0f), c2 = fmaxf(p2, 0.0f);
        float csum = fmaxf(c0 + c1 + c2, 1e-10f);
        c0 /= csum; c1 /= csum; c2 /= csum;
        float zpix = c0*z0 + c1*z1 + c2*z2;

        float d2 = fminf(fminf(seg_d2(px, py, ax, ay, bx, by),
                               seg_d2(px, py, bx, by, cx, cy)),
                         seg_d2(px, py, cx, cy, ax, ay));
        float sd = inside ? -d2 : d2;
        bool valid = (sd < 1e-4f) && (zpix > 1e-4f);
        if (!valid) continue;

        float uu = c0*fd[13] + c1*fd[15] + c2*fd[17];
        float vv = c0*fd[14] + c1*fd[16] + c2*fd[18];

        if (zpix < tz[KF-1] || (zpix == tz[KF-1] && f < ti[KF-1])) {
            float nz = zpix, nd = sd, nu = uu, nv = vv;
            int ni = f;
            #pragma unroll
            for (int k = 0; k < KF; k++) {
                bool sw = (nz < tz[k]) || (nz == tz[k] && ni < ti[k]);
                if (sw) {
                    float tf;
                    tf = tz[k]; tz[k] = nz; nz = tf;
                    tf = td[k]; td[k] = nd; nd = tf;
                    tf = tu[k]; tu[k] = nu; nu = tf;
                    tf = tv[k]; tv[k] = nv; nv = tf;
                    int tmpi = ti[k]; ti[k] = ni; ni = tmpi;
                }
            }
        }
    }

    // ---- shading epilogue ----
    float prob[KF], zinv[KF], zks[KF];
    float zmax = 1e-10f;
    #pragma unroll
    for (int k = 0; k < KF; k++) {
        bool vk = (tz[k] < 1e30f);
        float sg = 1.0f / (1.0f + expf(td[k] / 1e-4f));   // sigmoid(-d/SIGMA)
        prob[k] = vk ? sg : 0.0f;
        zks[k]  = vk ? tz[k] : 100.0f;
        zinv[k] = vk ? (100.0f - tz[k]) / 99.0f : 0.0f;
        zmax = fmaxf(zmax, zinv[k]);
    }

    float rs = 0.0f, gs = 0.0f, bs = 0.0f, ws = 0.0f, ds = 0.0f, oma = 1.0f;
    #pragma unroll
    for (int k = 0; k < KF; k++) {
        float w = prob[k] * expf((zinv[k] - zmax) / 1e-4f);
        oma *= (1.0f - prob[k]);
        ws += w;
        ds += w * zks[k];
        if (prob[k] > 0.0f) {
            float txc = tu[k] * 127.0f;
            float tyc = (1.0f - tv[k]) * 127.0f;
            float x0f = fminf(fmaxf(floorf(txc), 0.0f), 127.0f);
            float y0f = fminf(fmaxf(floorf(tyc), 0.0f), 127.0f);
            int x0 = (int)x0f, y0 = (int)y0f;
            int x1 = min(x0 + 1, 127), y1 = min(y0 + 1, 127);
            float wx = txc - x0f, wy = tyc - y0f;
            const float* t00 = &tex[(y0 * 128 + x0) * 3];
            const float* t01 = &tex[(y0 * 128 + x1) * 3];
            const float* t10 = &tex[(y1 * 128 + x0) * 3];
            const float* t11 = &tex[(y1 * 128 + x1) * 3];
            #pragma unroll
            for (int c = 0; c < 3; c++) {
                float top = (1.0f - wx) * __ldg(&t00[c]) + wx * __ldg(&t01[c]);
                float bot = (1.0f - wx) * __ldg(&t10[c]) + wx * __ldg(&t11[c]);
                float col = (1.0f - wy) * top + wy * bot;
                if (c == 0) rs += w * col;
                else if (c == 1) gs += w * col;
                else bs += w * col;
            }
        }
    }

    float delta = expf((1e-10f - zmax) / 1e-4f);
    float denom = ws + delta;
    float invd = 1.0f / denom;

    int p = y * IMG + x;
    out[p*5 + 0] = rs * invd;                      // BG color is black
    out[p*5 + 1] = gs * invd;
    out[p*5 + 2] = bs * invd;
    out[p*5 + 3] = 1.0f - oma;
    out[p*5 + 4] = (ds + delta * 100.0f) * invd;   // Z_BACKGROUND = 100
}

// ---------------------------------------------------------------------------
extern "C" void kernel_launch(void* const* d_in, const int* in_sizes, int n_in,
                              void* d_out, int out_size) {
    const float* xy_off = (const float*)d_in[0];   // (1,289,2)
    const float* z_grid = (const float*)d_in[1];   // (1,289,1)
    const float* rgb_in = (const float*)d_in[2];   // (1,128,128,3)
    const float* R_in   = (const float*)d_in[3];   // (1,3,3)
    const float* T_in   = (const float*)d_in[4];   // (1,3)
    const float* R_out  = (const float*)d_in[5];   // (1,3,3)
    const float* T_out  = (const float*)d_in[6];   // (1,3)
    float* out = (float*)d_out;                    // (1,128,128,5)

    setup_kernel<<<1, NF>>>(xy_off, z_grid, R_in, T_in, R_out, T_out);
    raster_kernel<<<IMG, IMG>>>(rgb_in, out);
}

// round 3
// speedup vs baseline: 1.6571x; 1.6571x over previous
#include <cuda_runtime.h>
#include <math.h>

#define GRIDN 17
#define NV    289          // 17*17 vertices
#define NF    512          // faces
#define IMG   128
#define KF    8

#define TILE_PX   8        // 8x8 pixel tiles
#define TILES_X   16
#define TILES     256      // 16x16 tiles
#define TCAP      128      // faces per tile capacity (typ ~10)
#define FSTRIDE   23

// Per-face data (23 floats):
// 0:ax 1:ay 2:bx 3:by 4:cx 5:cy 6:z0 7:z1 8:z2 9:inv_area
// 10:z1*z2 11:z0*z2 12:z0*z1 13:u0 14:v0 15:u1 16:v1 17:u2 18:v2
// 19:bbx0 20:bbx1 21:bby0 22:bby1
__device__ float g_main[NF * FSTRIDE];
__device__ int   g_tcnt[TILES];
__device__ int   g_tlist[TILES * TCAP];

__device__ __forceinline__ int vid(int y, int x) { return y * GRIDN + x; }

__device__ __forceinline__ void face_idx(int f, int& i0, int& i1, int& i2) {
    int g = f >> 6, t = f & 63;
    int r = t >> 3, c = t & 7;
    int ny, nx;
    switch (g) {
        case 0:  ny = 2*r;   nx = 1+2*c; i0 = vid(ny,nx+1);   i1 = vid(ny,nx);   i2 = vid(ny+1,nx);   break;
        case 1:  ny = 2*r;   nx = 1+2*c; i0 = vid(ny,nx+1);   i1 = vid(ny+1,nx); i2 = vid(ny+1,nx+1); break;
        case 2:  ny = 2*r;   nx = 2*c;   i0 = vid(ny,nx+1);   i1 = vid(ny,nx);   i2 = vid(ny+1,nx+1); break;
        case 3:  ny = 2*r;   nx = 2*c;   i0 = vid(ny+1,nx+1); i1 = vid(ny,nx);   i2 = vid(ny+1,nx);   break;
        case 4:  ny = 1+2*r; nx = 2*c;   i0 = vid(ny,nx+1);   i1 = vid(ny,nx);   i2 = vid(ny+1,nx);   break;
        case 5:  ny = 1+2*r; nx = 2*c;   i0 = vid(ny,nx+1);   i1 = vid(ny+1,nx); i2 = vid(ny+1,nx+1); break;
        case 6:  ny = 1+2*r; nx = 1+2*c; i0 = vid(ny,nx+1);   i1 = vid(ny,nx);   i2 = vid(ny+1,nx+1); break;
        default: ny = 1+2*r; nx = 1+2*c; i0 = vid(ny+1,nx+1); i1 = vid(ny,nx);   i2 = vid(ny+1,nx);   break;
    }
}

// ---------------------------------------------------------------------------
// Kernel 1: vertex transform + per-face precompute + tile binning. <<<1,512>>>
// ---------------------------------------------------------------------------
__global__ void __launch_bounds__(NF) setup_kernel(
                             const float* __restrict__ xy_off,   // (1,289,2)
                             const float* __restrict__ z_grid,   // (1,289,1)
                             const float* __restrict__ R_in,     // (1,3,3)
                             const float* __restrict__ T_in,     // (1,3)
                             const float* __restrict__ R_out,    // (1,3,3)
                             const float* __restrict__ T_out)    // (1,3)
{
    const float SCALE = 0.57735026918962573f;     // tan(30 deg)
    const float SINV  = 1.0f / 0.57735026918962573f;

    __shared__ float ssx[NV], ssy[NV], ssz[NV];
    int t = threadIdx.x;

    if (t < TILES) g_tcnt[t] = 0;

    if (t < NV) {
        int vy = t / GRIDN, vx = t % GRIDN;
        float ux = -1.0f + 0.125f * (float)vx;
        float uy = -1.0f + 0.125f * (float)vy;
        float gx = (ux + xy_off[2*t + 0]) * SCALE;
        float gy = (uy + xy_off[2*t + 1]) * SCALE;
        float zg = z_grid[t];
        float s0 = gx * zg, s1 = gy * zg, s2 = zg;
        float q0 = s0 - T_in[0], q1 = s1 - T_in[1], q2 = s2 - T_in[2];
        float wx = R_in[0]*q0 + R_in[1]*q1 + R_in[2]*q2;
        float wy = R_in[3]*q0 + R_in[4]*q1 + R_in[5]*q2;
        float wz = R_in[6]*q0 + R_in[7]*q1 + R_in[8]*q2;
        float vxv = wx*R_out[0] + wy*R_out[3] + wz*R_out[6] + T_out[0];
        float vyv = wx*R_out[1] + wy*R_out[4] + wz*R_out[7] + T_out[1];
        float vzv = wx*R_out[2] + wy*R_out[5] + wz*R_out[8] + T_out[2];
        float zden = (vzv >= 0.0f) ? fmaxf(vzv, 0.01f) : fminf(vzv, -0.01f);
        ssx[t] = SINV * vxv / zden;
        ssy[t] = SINV * vyv / zden;
        ssz[t] = vzv;
    }
    __syncthreads();

    int f = t;  // 512 threads == 512 faces
    int i0, i1, i2;
    face_idx(f, i0, i1, i2);

    float ax = ssx[i0], ay = ssy[i0], z0 = ssz[i0];
    float bx = ssx[i1], by = ssy[i1], z1 = ssz[i1];
    float cx = ssx[i2], cy = ssy[i2], z2 = ssz[i2];

    float area = (bx - ax) * (cy - ay) - (by - ay) * (cx - ax);
    float area_s = (fabsf(area) < 1e-8f) ? 1e-8f : area;

    float u0 = 1.0f - 0.0625f * (float)(i0 % GRIDN), v0 = 0.0625f * (float)(i0 / GRIDN);
    float u1 = 1.0f - 0.0625f * (float)(i1 % GRIDN), v1 = 0.0625f * (float)(i1 / GRIDN);
    float u2 = 1.0f - 0.0625f * (float)(i2 % GRIDN), v2 = 0.0625f * (float)(i2 / GRIDN);

    const float M = 0.010001f;   // sqrt(BLUR_RADIUS) + eps
    float bbx0 = fminf(fminf(ax, bx), cx) - M;
    float bbx1 = fmaxf(fmaxf(ax, bx), cx) + M;
    float bby0 = fminf(fminf(ay, by), cy) - M;
    float bby1 = fmaxf(fmaxf(ay, by), cy) + M;

    float* fd = &g_main[f * FSTRIDE];
    fd[0]=ax; fd[1]=ay; fd[2]=bx; fd[3]=by; fd[4]=cx; fd[5]=cy;
    fd[6]=z0; fd[7]=z1; fd[8]=z2;
    fd[9]=1.0f/area_s;
    fd[10]=z1*z2; fd[11]=z0*z2; fd[12]=z0*z1;
    fd[13]=u0; fd[14]=v0; fd[15]=u1; fd[16]=v1; fd[17]=u2; fd[18]=v2;
    fd[19]=bbx0; fd[20]=bbx1; fd[21]=bby0; fd[22]=bby1;

    // ---- tile binning (conservative pixel range from NDC bbox) ----
    // px(x) = 1 - (2x+1)/128  (decreasing).  px<=bbx1 -> x >= (1-bbx1)*64-0.5
    int xlo = (int)floorf((1.0f - bbx1) * 64.0f - 0.5f);
    int xhi = (int)floorf((1.0f - bbx0) * 64.0f - 0.5f) + 1;
    int ylo = (int)floorf((1.0f - bby1) * 64.0f - 0.5f);
    int yhi = (int)floorf((1.0f - bby0) * 64.0f - 0.5f) + 1;
    xlo = max(xlo, 0); xhi = min(xhi, IMG - 1);
    ylo = max(ylo, 0); yhi = min(yhi, IMG - 1);
    if (xlo <= xhi && ylo <= yhi) {
        int txlo = xlo >> 3, txhi = xhi >> 3;
        int tylo = ylo >> 3, tyhi = yhi >> 3;
        for (int ty = tylo; ty <= tyhi; ty++)
            for (int tx = txlo; tx <= txhi; tx++) {
                int tb = ty * TILES_X + tx;
                int pos = atomicAdd(&g_tcnt[tb], 1);
                if (pos < TCAP) g_tlist[tb * TCAP + pos] = f;
            }
    }
}

__device__ __forceinline__ float seg_d2(float px, float py,
                                        float sx, float sy, float ex, float ey) {
    float dx = ex - sx, dy = ey - sy;
    float dd = fmaxf(dx*dx + dy*dy, 1e-12f);
    float tt = __fdividef((px - sx)*dx + (py - sy)*dy, dd);
    tt = fminf(fmaxf(tt, 0.0f), 1.0f);
    float qx = px - (sx + tt*dx), qy = py - (sy + tt*dy);
    return qx*qx + qy*qy;
}

// ---------------------------------------------------------------------------
// Kernel 2: rasterize + shade.  <<<256, 64>>> — one 8x8 tile per block.
// ---------------------------------------------------------------------------
__global__ void __launch_bounds__(64) raster_kernel(const float* __restrict__ tex,
                                                    float* __restrict__ out)
{
    __shared__ float sf[TCAP * FSTRIDE];
    __shared__ int   sl[TCAP];

    int b  = blockIdx.x;
    int tx = b & (TILES_X - 1), ty = b >> 4;
    int t  = threadIdx.x;
    int lx = t & (TILE_PX - 1), ly = t >> 3;
    int x  = tx * TILE_PX + lx;
    int y  = ty * TILE_PX + ly;

    float py = 1.0f - 2.0f * ((float)y + 0.5f) / 128.0f;
    float px = 1.0f - 2.0f * ((float)x + 0.5f) / 128.0f;

    int cnt = min(g_tcnt[b], TCAP);
    for (int i = t; i < cnt; i += 64) sl[i] = g_tlist[b * TCAP + i];
    __syncthreads();
    // per-face copy: thread i copies whole face i (no integer division)
    for (int fi = t; fi < cnt; fi += 64) {
        const float* src = &g_main[sl[fi] * FSTRIDE];
        float* dst = &sf[fi * FSTRIDE];
        #pragma unroll
        for (int j = 0; j < FSTRIDE; j++) dst[j] = src[j];
    }
    __syncthreads();

    // top-8 by (z, face index) lexicographic
    float tz[KF], td[KF], tu[KF], tv[KF];
    int   ti[KF];
    #pragma unroll
    for (int k = 0; k < KF; k++) {
        tz[k] = __int_as_float(0x7f800000);
        td[k] = 0.0f; tu[k] = 0.0f; tv[k] = 0.0f; ti[k] = 0x7fffffff;
    }

    for (int i = 0; i < cnt; i++) {
        const float* fd = &sf[i * FSTRIDE];
        if (px < fd[19] || px > fd[20] || py < fd[21] || py > fd[22]) continue;

        float ax = fd[0], ay = fd[1], bx = fd[2], by = fd[3], cx = fd[4], cy = fd[5];
        float z0 = fd[6], z1 = fd[7], z2 = fd[8];
        float inv_area = fd[9];
        float z12 = fd[10], z02 = fd[11], z01 = fd[12];

        float w0 = (bx - px)*(cy - py) - (by - py)*(cx - px);
        float w1 = (cx - px)*(ay - py) - (cy - py)*(ax - px);
        float w2 = (ax - px)*(by - py) - (ay - py)*(bx - px);
        float b0 = w0 * inv_area, b1 = w1 * inv_area, b2 = w2 * inv_area;
        bool inside = (b0 >= 0.0f) && (b1 >= 0.0f) && (b2 >= 0.0f);

        float n0 = b0 * z12, n1 = b1 * z02, n2 = b2 * z01;
        float den = n0 + n1 + n2;
        den = (fabsf(den) < 1e-10f) ? 1e-10f : den;
        float invden = 1.0f / den;                        // precise (feeds z)
        float c0 = fmaxf(n0 * invden, 0.0f);
        float c1 = fmaxf(n1 * invden, 0.0f);
        float c2 = fmaxf(n2 * invden, 0.0f);
        float invcs = 1.0f / fmaxf(c0 + c1 + c2, 1e-10f); // precise
        c0 *= invcs; c1 *= invcs; c2 *= invcs;
        float zpix = c0*z0 + c1*z1 + c2*z2;

        float d2 = fminf(fminf(seg_d2(px, py, ax, ay, bx, by),
                               seg_d2(px, py, bx, by, cx, cy)),
                         seg_d2(px, py, cx, cy, ax, ay));
        float sd = inside ? -d2 : d2;
        if (!((sd < 1e-4f) && (zpix > 1e-4f))) continue;

        float uu = c0*fd[13] + c1*fd[15] + c2*fd[17];
        float vv = c0*fd[14] + c1*fd[16] + c2*fd[18];
        int   f  = sl[i];

        if (zpix < tz[KF-1] || (zpix == tz[KF-1] && f < ti[KF-1])) {
            float nz = zpix, nd = sd, nu = uu, nv = vv;
            int ni = f;
            #pragma unroll
            for (int k = 0; k < KF; k++) {
                bool sw = (nz < tz[k]) || (nz == tz[k] && ni < ti[k]);
                if (sw) {
                    float tf;
                    tf = tz[k]; tz[k] = nz; nz = tf;
                    tf = td[k]; td[k] = nd; nd = tf;
                    tf = tu[k]; tu[k] = nu; nu = tf;
                    tf = tv[k]; tv[k] = nv; nv = tf;
                    int tmpi = ti[k]; ti[k] = ni; ni = tmpi;
                }
            }
        }
    }

    // ---- shading epilogue ----
    float prob[KF], zinv[KF], zks[KF];
    float zmax = 1e-10f;
    #pragma unroll
    for (int k = 0; k < KF; k++) {
        bool vk = (tz[k] < 1e30f);
        float sg = 1.0f / (1.0f + __expf(td[k] / 1e-4f));   // sigmoid(-d/SIGMA)
        prob[k] = vk ? sg : 0.0f;
        zks[k]  = vk ? tz[k] : 100.0f;
        zinv[k] = vk ? (100.0f - tz[k]) / 99.0f : 0.0f;
        zmax = fmaxf(zmax, zinv[k]);
    }

    float rs = 0.0f, gs = 0.0f, bs = 0.0f, ws = 0.0f, ds = 0.0f, oma = 1.0f;
    #pragma unroll
    for (int k = 0; k < KF; k++) {
        float w = prob[k] * __expf((zinv[k] - zmax) / 1e-4f);
        oma *= (1.0f - prob[k]);
        ws += w;
        ds += w * zks[k];
        if (prob[k] > 0.0f) {
            float txc = tu[k] * 127.0f;
            float tyc = (1.0f - tv[k]) * 127.0f;
            float x0f = fminf(fmaxf(floorf(txc), 0.0f), 127.0f);
            float y0f = fminf(fmaxf(floorf(tyc), 0.0f), 127.0f);
            int x0 = (int)x0f, y0 = (int)y0f;
            int x1 = min(x0 + 1, 127), y1 = min(y0 + 1, 127);
            float wx = txc - x0f, wy = tyc - y0f;
            const float* t00 = &tex[(y0 * 128 + x0) * 3];
            const float* t01 = &tex[(y0 * 128 + x1) * 3];
            const float* t10 = &tex[(y1 * 128 + x0) * 3];
            const float* t11 = &tex[(y1 * 128 + x1) * 3];
            #pragma unroll
            for (int c = 0; c < 3; c++) {
                float top = (1.0f - wx) * __ldg(&t00[c]) + wx * __ldg(&t01[c]);
                float bot = (1.0f - wx) * __ldg(&t10[c]) + wx * __ldg(&t11[c]);
                float col = (1.0f - wy) * top + wy * bot;
                if (c == 0) rs += w * col;
                else if (c == 1) gs += w * col;
                else bs += w * col;
            }
        }
    }

    float delta = __expf((1e-10f - zmax) / 1e-4f);
    float invd = 1.0f / (ws + delta);

    int p = y * IMG + x;
    out[p*5 + 0] = rs * invd;
    out[p*5 + 1] = gs * invd;
    out[p*5 + 2] = bs * invd;
    out[p*5 + 3] = 1.0f - oma;
    out[p*5 + 4] = (ds + delta * 100.0f) * invd;
}

// ---------------------------------------------------------------------------
extern "C" void kernel_launch(void* const* d_in, const int* in_sizes, int n_in,
                              void* d_out, int out_size) {
    const float* xy_off = (const float*)d_in[0];
    const float* z_grid = (const float*)d_in[1];
    const float* rgb_in = (const float*)d_in[2];
    const float* R_in   = (const float*)d_in[3];
    const float* T_in   = (const float*)d_in[4];
    const float* R_out  = (const float*)d_in[5];
    const float* T_out  = (const float*)d_in[6];
    float* out = (float*)d_out;

    setup_kernel<<<1, NF>>>(xy_off, z_grid, R_in, T_in, R_out, T_out);
    raster_kernel<<<TILES, 64>>>(rgb_in, out);
}

// round 7
// speedup vs baseline: 2.6378x; 1.5918x over previous
#include <cuda_runtime.h>
#include <math.h>

#define GRIDN 17
#define NV    289
#define NF    512
#define IMG   128
#define KF    8

#define TILE_PX   8
#define TILES_X   16
#define TILES     256
#define TCAP      64       // faces per tile capacity (typ ~10-20)

__device__ __forceinline__ int vid(int y, int x) { return y * GRIDN + x; }

__device__ __forceinline__ void face_idx(int f, int& i0, int& i1, int& i2) {
    int g = f >> 6, t = f & 63;
    int r = t >> 3, c = t & 7;
    int ny, nx;
    switch (g) {
        case 0:  ny = 2*r;   nx = 1+2*c; i0 = vid(ny,nx+1);   i1 = vid(ny,nx);   i2 = vid(ny+1,nx);   break;
        case 1:  ny = 2*r;   nx = 1+2*c; i0 = vid(ny,nx+1);   i1 = vid(ny+1,nx); i2 = vid(ny+1,nx+1); break;
        case 2:  ny = 2*r;   nx = 2*c;   i0 = vid(ny,nx+1);   i1 = vid(ny,nx);   i2 = vid(ny+1,nx+1); break;
        case 3:  ny = 2*r;   nx = 2*c;   i0 = vid(ny+1,nx+1); i1 = vid(ny,nx);   i2 = vid(ny+1,nx);   break;
        case 4:  ny = 1+2*r; nx = 2*c;   i0 = vid(ny,nx+1);   i1 = vid(ny,nx);   i2 = vid(ny+1,nx);   break;
        case 5:  ny = 1+2*r; nx = 2*c;   i0 = vid(ny,nx+1);   i1 = vid(ny+1,nx); i2 = vid(ny+1,nx+1); break;
        case 6:  ny = 1+2*r; nx = 1+2*c; i0 = vid(ny,nx+1);   i1 = vid(ny,nx);   i2 = vid(ny+1,nx+1); break;
        default: ny = 1+2*r; nx = 1+2*c; i0 = vid(ny+1,nx+1); i1 = vid(ny,nx);   i2 = vid(ny+1,nx);   break;
    }
}

__device__ __forceinline__ float seg_d2(float px, float py,
                                        float sx, float sy, float ex, float ey) {
    float dx = ex - sx, dy = ey - sy;
    float dd = fmaxf(dx*dx + dy*dy, 1e-12f);
    float tt = __fdividef((px - sx)*dx + (py - sy)*dy, dd);
    tt = fminf(fmaxf(tt, 0.0f), 1.0f);
    float qx = px - (sx + tt*dx), qy = py - (sy + tt*dy);
    return qx*qx + qy*qy;
}

// ---------------------------------------------------------------------------
// Fused kernel: <<<256, 64>>>.  One 8x8 pixel tile per block.
// Each block: (1) transform all 289 vertices into smem, (2) cull 512 faces
// against its tile rect + build face records, (3) per-pixel top-8 + shade.
// ---------------------------------------------------------------------------
__global__ void __launch_bounds__(64) fused_kernel(
                             const float* __restrict__ xy_off,   // (1,289,2)
                             const float* __restrict__ z_grid,   // (1,289,1)
                             const float* __restrict__ tex,      // (1,128,128,3)
                             const float* __restrict__ R_in,     // (1,3,3)
                             const float* __restrict__ T_in,     // (1,3)
                             const float* __restrict__ R_out,    // (1,3,3)
                             const float* __restrict__ T_out,    // (1,3)
                             float* __restrict__ out)            // (1,128,128,5)
{
    const float SCALE = 0.57735026918962573f;   // tan(30 deg)
    const float SINV  = 1.0f / 0.57735026918962573f;

    __shared__ float  ssx[NV], ssy[NV], ssz[NV];
    __shared__ float4 sq[TCAP * 6];
    __shared__ int    s_cnt;

    int b  = blockIdx.x;
    int tx = b & (TILES_X - 1), ty = b >> 4;
    int t  = threadIdx.x;

    if (t == 0) s_cnt = 0;

    // ---- broadcast camera params (same addresses across threads; L2 hit) ----
    float ri0=R_in[0], ri1=R_in[1], ri2=R_in[2], ri3=R_in[3], ri4=R_in[4];
    float ri5=R_in[5], ri6=R_in[6], ri7=R_in[7], ri8=R_in[8];
    float ti0=T_in[0], ti1=T_in[1], ti2=T_in[2];
    float ro0=R_out[0], ro1=R_out[1], ro2=R_out[2], ro3=R_out[3], ro4=R_out[4];
    float ro5=R_out[5], ro6=R_out[6], ro7=R_out[7], ro8=R_out[8];
    float to0=T_out[0], to1=T_out[1], to2=T_out[2];

    // ---- vertex transform (289 verts / 64 threads = 5 iters) ----
    for (int v = t; v < NV; v += 64) {
        int vy = v / GRIDN, vx = v % GRIDN;
        float ux = -1.0f + 0.125f * (float)vx;
        float uy = -1.0f + 0.125f * (float)vy;
        float gx = (ux + xy_off[2*v + 0]) * SCALE;
        float gy = (uy + xy_off[2*v + 1]) * SCALE;
        float zg = z_grid[v];
        float q0 = gx*zg - ti0, q1 = gy*zg - ti1, q2 = zg - ti2;
        float wx = ri0*q0 + ri1*q1 + ri2*q2;
        float wy = ri3*q0 + ri4*q1 + ri5*q2;
        float wz = ri6*q0 + ri7*q1 + ri8*q2;
        float vxv = wx*ro0 + wy*ro3 + wz*ro6 + to0;
        float vyv = wx*ro1 + wy*ro4 + wz*ro7 + to1;
        float vzv = wx*ro2 + wy*ro5 + wz*ro8 + to2;
        float zden = (vzv >= 0.0f) ? fmaxf(vzv, 0.01f) : fminf(vzv, -0.01f);
        ssx[v] = SINV * vxv / zden;
        ssy[v] = SINV * vyv / zden;
        ssz[v] = vzv;
    }
    __syncthreads();

    // tile NDC rect (px decreasing in x): x in [8tx, 8tx+7]
    float px_hi = 1.0f - (float)(16*tx + 1)  / 128.0f;
    float px_lo = 1.0f - (float)(16*tx + 15) / 128.0f;
    float py_hi = 1.0f - (float)(16*ty + 1)  / 128.0f;
    float py_lo = 1.0f - (float)(16*ty + 15) / 128.0f;

    // ---- cull 512 faces (8 per thread), build records for survivors ----
    const float M = 0.010001f;   // sqrt(BLUR_RADIUS) + eps
    for (int f = t; f < NF; f += 64) {
        int i0, i1, i2;
        face_idx(f, i0, i1, i2);
        float ax = ssx[i0], ay = ssy[i0];
        float bx = ssx[i1], by = ssy[i1];
        float cx = ssx[i2], cy = ssy[i2];
        float bbx0 = fminf(fminf(ax, bx), cx) - M;
        float bbx1 = fmaxf(fmaxf(ax, bx), cx) + M;
        float bby0 = fminf(fminf(ay, by), cy) - M;
        float bby1 = fmaxf(fmaxf(ay, by), cy) + M;
        if (bbx0 <= px_hi && bbx1 >= px_lo && bby0 <= py_hi && bby1 >= py_lo) {
            int pos = atomicAdd(&s_cnt, 1);
            if (pos < TCAP) {
                float z0 = ssz[i0], z1 = ssz[i1], z2 = ssz[i2];
                float area = (bx - ax)*(cy - ay) - (by - ay)*(cx - ax);
                float area_s = (fabsf(area) < 1e-8f) ? 1e-8f : area;
                float u0 = 1.0f - 0.0625f*(float)(i0 % GRIDN), v0 = 0.0625f*(float)(i0 / GRIDN);
                float u1 = 1.0f - 0.0625f*(float)(i1 % GRIDN), v1 = 0.0625f*(float)(i1 / GRIDN);
                float u2 = 1.0f - 0.0625f*(float)(i2 % GRIDN), v2 = 0.0625f*(float)(i2 / GRIDN);
                float4* q = &sq[pos * 6];
                q[0] = make_float4(bbx0, bbx1, bby0, bby1);
                q[1] = make_float4(ax, ay, bx, by);
                q[2] = make_float4(cx, cy, z0, z1);
                q[3] = make_float4(z2, 1.0f/area_s, z1*z2, z0*z2);
                q[4] = make_float4(z0*z1, u0, v0, u1);
                q[5] = make_float4(v1, u2, v2, __int_as_float(f));
            }
        }
    }
    __syncthreads();
    int cnt = min(s_cnt, TCAP);

    // ---- per-pixel rasterization ----
    int lx = t & (TILE_PX - 1), ly = t >> 3;
    int x  = tx * TILE_PX + lx;
    int y  = ty * TILE_PX + ly;
    float py = 1.0f - 2.0f * ((float)y + 0.5f) / 128.0f;
    float px = 1.0f - 2.0f * ((float)x + 0.5f) / 128.0f;

    float tz[KF], td[KF], tu[KF], tv[KF];
    int   ti[KF];
    #pragma unroll
    for (int k = 0; k < KF; k++) {
        tz[k] = __int_as_float(0x7f800000);
        td[k] = 0.0f; tu[k] = 0.0f; tv[k] = 0.0f; ti[k] = 0x7fffffff;
    }

    for (int i = 0; i < cnt; i++) {
        const float4* q = &sq[i * 6];
        float4 q0 = q[0];
        if (px < q0.x || px > q0.y || py < q0.z || py > q0.w) continue;

        float4 q1 = q[1], q2 = q[2], q3 = q[3], q4 = q[4], q5 = q[5];
        float ax = q1.x, ay = q1.y, bx = q1.z, by = q1.w;
        float cx = q2.x, cy = q2.y, z0 = q2.z, z1 = q2.w;
        float z2 = q3.x, inv_area = q3.y, z12 = q3.z, z02 = q3.w;
        float z01 = q4.x;

        float w0 = (bx - px)*(cy - py) - (by - py)*(cx - px);
        float w1 = (cx - px)*(ay - py) - (cy - py)*(ax - px);
        float w2 = (ax - px)*(by - py) - (ay - py)*(bx - px);
        float b0 = w0 * inv_area, b1 = w1 * inv_area, b2 = w2 * inv_area;
        bool inside = (b0 >= 0.0f) && (b1 >= 0.0f) && (b2 >= 0.0f);

        float n0 = b0 * z12, n1 = b1 * z02, n2 = b2 * z01;
        float den = n0 + n1 + n2;
        den = (fabsf(den) < 1e-10f) ? 1e-10f : den;
        float invden = __fdividef(1.0f, den);
        float c0 = fmaxf(n0 * invden, 0.0f);
        float c1 = fmaxf(n1 * invden, 0.0f);
        float c2 = fmaxf(n2 * invden, 0.0f);
        float invcs = __fdividef(1.0f, fmaxf(c0 + c1 + c2, 1e-10f));
        c0 *= invcs; c1 *= invcs; c2 *= invcs;
        float zpix = c0*z0 + c1*z1 + c2*z2;

        float d2 = fminf(fminf(seg_d2(px, py, ax, ay, bx, by),
                               seg_d2(px, py, bx, by, cx, cy)),
                         seg_d2(px, py, cx, cy, ax, ay));
        float sd = inside ? -d2 : d2;
        if (!((sd < 1e-4f) && (zpix > 1e-4f))) continue;

        float uu = c0*q4.y + c1*q4.w + c2*q5.y;
        float vv = c0*q4.z + c1*q5.x + c2*q5.z;
        int   f  = __float_as_int(q5.w);

        if (zpix < tz[KF-1] || (zpix == tz[KF-1] && f < ti[KF-1])) {
            float nz = zpix, nd = sd, nu = uu, nv = vv;
            int ni = f;
            #pragma unroll
            for (int k = 0; k < KF; k++) {
                bool sw = (nz < tz[k]) || (nz == tz[k] && ni < ti[k]);
                if (sw) {
                    float tf;
                    tf = tz[k]; tz[k] = nz; nz = tf;
                    tf = td[k]; td[k] = nd; nd = tf;
                    tf = tu[k]; tu[k] = nu; nu = tf;
                    tf = tv[k]; tv[k] = nv; nv = tf;
                    int tmpi = ti[k]; ti[k] = ni; ni = tmpi;
                }
            }
        }
    }

    // ---- shading epilogue ----
    float prob[KF], zinv[KF], zks[KF];
    float zmax = 1e-10f;
    #pragma unroll
    for (int k = 0; k < KF; k++) {
        bool vk = (tz[k] < 1e30f);
        float sg = 1.0f / (1.0f + __expf(td[k] / 1e-4f));   // sigmoid(-d/SIGMA)
        prob[k] = vk ? sg : 0.0f;
        zks[k]  = vk ? tz[k] : 100.0f;
        zinv[k] = vk ? (100.0f - tz[k]) / 99.0f : 0.0f;
        zmax = fmaxf(zmax, zinv[k]);
    }

    float rs = 0.0f, gs = 0.0f, bs = 0.0f, ws = 0.0f, ds = 0.0f, oma = 1.0f;
    #pragma unroll
    for (int k = 0; k < KF; k++) {
        float w = prob[k] * __expf((zinv[k] - zmax) / 1e-4f);
        oma *= (1.0f - prob[k]);
        ws += w;
        ds += w * zks[k];
        if (prob[k] > 0.0f) {
            float txc = tu[k] * 127.0f;
            float tyc = (1.0f - tv[k]) * 127.0f;
            float x0f = fminf(fmaxf(floorf(txc), 0.0f), 127.0f);
            float y0f = fminf(fmaxf(floorf(tyc), 0.0f), 127.0f);
            int x0 = (int)x0f, y0 = (int)y0f;
            int x1 = min(x0 + 1, 127), y1 = min(y0 + 1, 127);
            float wx = txc - x0f, wy = tyc - y0f;
            const float* t00 = &tex[(y0 * 128 + x0) * 3];
            const float* t01 = &tex[(y0 * 128 + x1) * 3];
            const float* t10 = &tex[(y1 * 128 + x0) * 3];
            const float* t11 = &tex[(y1 * 128 + x1) * 3];
            #pragma unroll
            for (int c = 0; c < 3; c++) {
                float top = (1.0f - wx) * __ldg(&t00[c]) + wx * __ldg(&t01[c]);
                float bot = (1.0f - wx) * __ldg(&t10[c]) + wx * __ldg(&t11[c]);
                float col = (1.0f - wy) * top + wy * bot;
                if (c == 0) rs += w * col;
                else if (c == 1) gs += w * col;
                else bs += w * col;
            }
        }
    }

    float delta = __expf((1e-10f - zmax) / 1e-4f);
    float invd = 1.0f / (ws + delta);

    int p = y * IMG + x;
    out[p*5 + 0] = rs * invd;
    out[p*5 + 1] = gs * invd;
    out[p*5 + 2] = bs * invd;
    out[p*5 + 3] = 1.0f - oma;
    out[p*5 + 4] = (ds + delta * 100.0f) * invd;
}

// ---------------------------------------------------------------------------
extern "C" void kernel_launch(void* const* d_in, const int* in_sizes, int n_in,
                              void* d_out, int out_size) {
    const float* xy_off = (const float*)d_in[0];
    const float* z_grid = (const float*)d_in[1];
    const float* rgb_in = (const float*)d_in[2];
    const float* R_in   = (const float*)d_in[3];
    const float* T_in   = (const float*)d_in[4];
    const float* R_out  = (const float*)d_in[5];
    const float* T_out  = (const float*)d_in[6];
    float* out = (float*)d_out;

    fused_kernel<<<TILES, 64>>>(xy_off, z_grid, rgb_in,
                                R_in, T_in, R_out, T_out, out);
}